// round 16
// baseline (speedup 1.0000x reference)
#include <cuda_runtime.h>
#include <cstdint>

// ---------------------------------------------------------------------------
// Problem constants (hardcoded from the reference)
// ---------------------------------------------------------------------------
#define N_B    8
#define LQ     300
#define NQ     2400        // N_B * LQ
#define C_DIM  256
#define HEADS  8
#define NLVL   4
#define NPTS   8
#define LEN_IN 21760
// level starts: 0, 16384, 20480, 21504  (sizes 128^2, 64^2, 32^2, 16^2)

// ---------------------------------------------------------------------------
// Scratch (device globals — no allocation allowed)
// ---------------------------------------------------------------------------
__device__ uint32_t g_packed[NQ * 512];          // 1-bit mask per (n,q): 128x128 bits
__device__ float    g_boxes[NQ * 4];             // cx, cy, w, h
__device__ float    g_locs[NQ * 512];            // 256 points * (x,y)
__device__ float    g_wts[NQ * 256];             // softmaxed weights
__device__ float    g_outcore[NQ * 256];         // pre-output-projection

// ---------------------------------------------------------------------------
// cp.async helpers
// ---------------------------------------------------------------------------
__device__ __forceinline__ uint32_t s2u(const void* p) {
    return (uint32_t)__cvta_generic_to_shared(p);
}
__device__ __forceinline__ void cp16(uint32_t dst, const void* src) {
    asm volatile("cp.async.cg.shared.global [%0], [%1], 16;" :: "r"(dst), "l"(src));
}
#define CP_COMMIT()  asm volatile("cp.async.commit_group;" ::: "memory")
#define CP_WAIT_1()  asm volatile("cp.async.wait_group 1;" ::: "memory")
#define CP_WAIT_0()  asm volatile("cp.async.wait_group 0;" ::: "memory")

// ---------------------------------------------------------------------------
// Kernel 1: bounding boxes + packed binary masks  (pure float4 streamer)
// grid = NQ blocks, 256 threads. Thread t handles 64 contiguous elements.
// ---------------------------------------------------------------------------
__global__ __launch_bounds__(256) void kbox(const float* __restrict__ masks)
{
    int nq   = blockIdx.x;
    int tid  = threadIdx.x;
    int row  = tid >> 1;
    int half = tid & 1;

    __shared__ unsigned scol[4];   // per-x "any over y" bits (128 cols)
    __shared__ unsigned srow[4];   // per-y "any over x" bits (128 rows)
    if (tid < 4) { scol[tid] = 0u; srow[tid] = 0u; }
    __syncthreads();

    const float4* p = (const float4*)(masks + (size_t)nq * 16384 + tid * 64);

    unsigned w0 = 0u, w1 = 0u;
    #pragma unroll
    for (int j = 0; j < 8; ++j) {
        float4 v = p[j];
        unsigned b = (v.x > 0.0f ? 1u : 0u)
                   | (v.y > 0.0f ? 2u : 0u)
                   | (v.z > 0.0f ? 4u : 0u)
                   | (v.w > 0.0f ? 8u : 0u);
        w0 |= b << (j * 4);
    }
    #pragma unroll
    for (int j = 8; j < 16; ++j) {
        float4 v = p[j];
        unsigned b = (v.x > 0.0f ? 1u : 0u)
                   | (v.y > 0.0f ? 2u : 0u)
                   | (v.z > 0.0f ? 4u : 0u)
                   | (v.w > 0.0f ? 8u : 0u);
        w1 |= b << ((j - 8) * 4);
    }

    uint32_t* pk = g_packed + (size_t)nq * 512 + row * 4 + half * 2;
    pk[0] = w0;
    pk[1] = w1;

    if (w0) atomicOr(&scol[half * 2], w0);
    if (w1) atomicOr(&scol[half * 2 + 1], w1);

    unsigned any = (w0 | w1) ? 1u : 0u;
    unsigned both = any | __shfl_xor_sync(0xffffffffu, any, 1);
    if (half == 0 && both)
        atomicOr(&srow[row >> 5], 1u << (row & 31));
    __syncthreads();

    if (tid == 0) {
        unsigned anyc = scol[0] | scol[1] | scol[2] | scol[3];
        float bx0 = 0.f, bx1 = 0.f, bx2 = 0.f, bx3 = 0.f;
        if (anyc) {
            int xmin = 0, xmax = 0, ymin = 0, ymax = 0;
            #pragma unroll
            for (int i = 3; i >= 0; --i) if (scol[i]) xmin = i * 32 + __ffs((int)scol[i]) - 1;
            #pragma unroll
            for (int i = 0; i < 4; ++i)  if (scol[i]) xmax = i * 32 + 31 - __clz((int)scol[i]);
            #pragma unroll
            for (int i = 3; i >= 0; --i) if (srow[i]) ymin = i * 32 + __ffs((int)srow[i]) - 1;
            #pragma unroll
            for (int i = 0; i < 4; ++i)  if (srow[i]) ymax = i * 32 + 31 - __clz((int)srow[i]);
            float x0 = xmin * (1.0f / 128.0f), x1 = (xmax + 1) * (1.0f / 128.0f);
            float y0 = ymin * (1.0f / 128.0f), y1 = (ymax + 1) * (1.0f / 128.0f);
            bx0 = (x0 + x1) * 0.5f;
            bx1 = (y0 + y1) * 0.5f;
            bx2 = x1 - x0;
            bx3 = y1 - y0;
        }
        *(float4*)(g_boxes + nq * 4) = make_float4(bx0, bx1, bx2, bx3);
    }
}

// ---------------------------------------------------------------------------
// Kernel 2 (fused): projections (cp.async double-buffered), locations,
// point-in-mask, per-head softmax.
// grid = 150 blocks (16 queries), 256 threads.
// dyn smem: qs[16*256] + 2 x wtile[16*768]   (112 KB)
// ---------------------------------------------------------------------------
__device__ __forceinline__ void stage_pp(const float* __restrict__ Woff,
                                         const float* __restrict__ Wattn,
                                         int k0, float* buf, int tid)
{
    #pragma unroll
    for (int j = 0; j < 12; ++j) {
        int idx = tid + j * 256;               // float4 index in tile, 0..3071
        int r   = idx / 192;                   // 192 float4 per row (512+256 floats)
        int c4  = idx - r * 192;
        const float* src = (c4 < 128)
            ? (Woff  + (size_t)(k0 + r) * 512 + c4 * 4)
            : (Wattn + (size_t)(k0 + r) * 256 + (c4 - 128) * 4);
        cp16(s2u(buf + r * 768 + c4 * 4), src);
    }
    CP_COMMIT();
}

__global__ __launch_bounds__(256) void kprojpts(const float* __restrict__ query,
                                                const float* __restrict__ Woff,
                                                const float* __restrict__ boff,
                                                const float* __restrict__ Wattn,
                                                const float* __restrict__ battn)
{
    extern __shared__ float sm[];
    float* qs  = sm;                 // 4096 floats
    float* wb0 = sm + 4096;          // 12288 floats
    float* wb1 = sm + 4096 + 12288;  // 12288 floats

    int tid = threadIdx.x;
    int q0  = blockIdx.x * 16;

    stage_pp(Woff, Wattn, 0,  wb0, tid);
    stage_pp(Woff, Wattn, 16, wb1, tid);

    for (int i = tid; i < 16 * 256; i += 256)
        qs[i] = query[(size_t)q0 * 256 + i];

    float acc0[16], acc1[16], acc2[16];
    #pragma unroll
    for (int i = 0; i < 16; ++i) { acc0[i] = 0.f; acc1[i] = 0.f; acc2[i] = 0.f; }

    for (int t = 0; t < 16; ++t) {
        if (t < 15) { CP_WAIT_1(); } else { CP_WAIT_0(); }
        __syncthreads();
        const float* buf = (t & 1) ? wb1 : wb0;
        #pragma unroll 4
        for (int r = 0; r < 16; ++r) {
            float w0 = buf[r * 768 + tid];
            float w1 = buf[r * 768 + 256 + tid];
            float w2 = buf[r * 768 + 512 + tid];
            int k = t * 16 + r;
            #pragma unroll
            for (int i = 0; i < 16; ++i) {
                float qv = qs[i * 256 + k];
                acc0[i] = fmaf(qv, w0, acc0[i]);
                acc1[i] = fmaf(qv, w1, acc1[i]);
                acc2[i] = fmaf(qv, w2, acc2[i]);
            }
        }
        __syncthreads();
        if (t + 2 < 16)
            stage_pp(Woff, Wattn, (t + 2) * 16, (t & 1) ? wb1 : wb0, tid);
    }

    // write projection results (+bias) into the wb0 region: res[16][768]
    float* res = wb0;
    {
        float b0 = boff[tid], b1 = boff[256 + tid], b2 = battn[tid];
        #pragma unroll
        for (int i = 0; i < 16; ++i) {
            res[i * 768 + tid]       = acc0[i] + b0;
            res[i * 768 + 256 + tid] = acc1[i] + b1;
            res[i * 768 + 512 + tid] = acc2[i] + b2;
        }
    }
    __syncthreads();

    // Phase B: thread tid = sample s (warp = head)
    int s = tid;
    for (int qi = 0; qi < 16; ++qi) {
        int nq = q0 + qi;
        float4 bx = *(const float4*)(g_boxes + nq * 4);
        float ox = res[qi * 768 + 2 * s];
        float oy = res[qi * 768 + 2 * s + 1];
        float at = res[qi * 768 + 512 + s];

        float lx = bx.x + ox * (bx.z * 0.0625f);
        float ly = bx.y + oy * (bx.w * 0.0625f);

        int px = (int)(lx * 128.0f); px = min(max(px, 0), 127);
        int py = (int)(ly * 128.0f); py = min(max(py, 0), 127);
        unsigned bit = (g_packed[(size_t)nq * 512 + py * 4 + (px >> 5)] >> (px & 31)) & 1u;

        float e = at * (float)bit;

        float mx = e;
        #pragma unroll
        for (int o = 16; o > 0; o >>= 1) mx = fmaxf(mx, __shfl_xor_sync(0xffffffffu, mx, o));
        float ex = expf(e - mx);
        float smv = ex;
        #pragma unroll
        for (int o = 16; o > 0; o >>= 1) smv += __shfl_xor_sync(0xffffffffu, smv, o);
        float w = ex / smv;

        ((float2*)(g_locs + (size_t)nq * 512))[s] = make_float2(lx, ly);
        g_wts[(size_t)nq * 256 + s] = w;
    }
}

// ---------------------------------------------------------------------------
// Kernel 3 (hot, fused): bilinear gather + weighted aggregation + per-head
// value projection. grid = NQ blocks, 8 warps (warp = head).
// Main loop: lane owns 8 channels. Epilogue: agg spilled to smem (per-warp
// segment, __syncwarp only), lane d computes outcore[nq, 32h+d] directly.
// ---------------------------------------------------------------------------
__global__ __launch_bounds__(256) void ksamp(const float* __restrict__ input,
                                             const float* __restrict__ Wval,
                                             const float* __restrict__ bval)
{
    __shared__ float sagg[8 * 256];

    int nq   = blockIdx.x;
    int n    = nq / LQ;
    int warp = threadIdx.x >> 5;
    int lane = threadIdx.x & 31;

    const float* base = input + (size_t)n * (LEN_IN * C_DIM);

    float2 L = ((const float2*)(g_locs + (size_t)nq * 512))[warp * 32 + lane];
    float  Wt = g_wts[(size_t)nq * 256 + warp * 32 + lane];
    float  Lx = L.x, Ly = L.y;

    float acc[8] = {0.f, 0.f, 0.f, 0.f, 0.f, 0.f, 0.f, 0.f};
    float bacc = 0.f;   // warp-uniform (cw is identical across lanes)

#define CORNER(XI, YI, CWV)                                                     \
    do {                                                                        \
        int _x = (XI), _y = (YI);                                               \
        if (_x >= 0 && _x < Wl && _y >= 0 && _y < Wl) {                         \
            float _cw = (CWV);                                                  \
            const float4* _r = (const float4*)(baseL +                          \
                               (size_t)(_y * Wl + _x) * C_DIM);                 \
            float4 _v0 = _r[lane];                                              \
            float4 _v1 = _r[32 + lane];                                         \
            acc[0] = fmaf(_cw, _v0.x, acc[0]);                                  \
            acc[1] = fmaf(_cw, _v0.y, acc[1]);                                  \
            acc[2] = fmaf(_cw, _v0.z, acc[2]);                                  \
            acc[3] = fmaf(_cw, _v0.w, acc[3]);                                  \
            acc[4] = fmaf(_cw, _v1.x, acc[4]);                                  \
            acc[5] = fmaf(_cw, _v1.y, acc[5]);                                  \
            acc[6] = fmaf(_cw, _v1.z, acc[6]);                                  \
            acc[7] = fmaf(_cw, _v1.w, acc[7]);                                  \
            bacc += _cw;                                                        \
        }                                                                       \
    } while (0)

    #pragma unroll
    for (int l = 0; l < 4; ++l) {
        const int Wl     = 128 >> l;
        const int startl = (l == 0) ? 0 : (l == 1) ? 16384 : (l == 2) ? 20480 : 21504;
        const float fW   = (float)Wl;
        const float* baseL = base + (size_t)startl * C_DIM;
        #pragma unroll
        for (int p = 0; p < 8; ++p) {
            int s = l * 8 + p;
            float lx = __shfl_sync(0xffffffffu, Lx, s);
            float ly = __shfl_sync(0xffffffffu, Ly, s);
            float wt = __shfl_sync(0xffffffffu, Wt, s);

            float px = lx * fW - 0.5f;
            float py = ly * fW - 0.5f;
            float xf = floorf(px), yf = floorf(py);
            float fx = px - xf,    fy = py - yf;
            int   x0 = (int)xf,    y0 = (int)yf;
            float gx = 1.0f - fx,  gy = 1.0f - fy;

            CORNER(x0,     y0,     wt * gx * gy);
            CORNER(x0 + 1, y0,     wt * fx * gy);
            CORNER(x0,     y0 + 1, wt * gx * fy);
            CORNER(x0 + 1, y0 + 1, wt * fx * fy);
        }
    }
#undef CORNER

    // spill aggregated 256-vector to this warp's smem segment
    float4* sp = (float4*)(sagg + warp * 256);
    sp[lane]      = make_float4(acc[0], acc[1], acc[2], acc[3]);
    sp[32 + lane] = make_float4(acc[4], acc[5], acc[6], acc[7]);
    __syncwarp();

    // per-head value projection: lane d computes out[32*warp + d]
    // Wval row-major [c][256]; warp reads 128B-coalesced slices (L1/L2-hot)
    const float* sa = sagg + warp * 256;
    const float* wp = Wval + warp * 32 + lane;
    float o = 0.f;
    #pragma unroll 8
    for (int c = 0; c < 256; ++c)
        o = fmaf(sa[c], wp[(size_t)c * 256], o);

    o += bacc * bval[warp * 32 + lane];
    g_outcore[(size_t)nq * 256 + warp * 32 + lane] = o;
}

// ---------------------------------------------------------------------------
// Kernel 4: output projection with cp.async double-buffered weight tiles
// grid = 300 blocks (8 queries), 256 threads.
// dyn smem: xs[8*256] + 2 x wtile[32*256]  (72 KB)
// ---------------------------------------------------------------------------
__device__ __forceinline__ void stage_out(const float* __restrict__ W,
                                          int k0, float* buf, int tid)
{
    #pragma unroll
    for (int j = 0; j < 8; ++j) {
        int f4 = tid + j * 256;          // 0..2047
        int r  = f4 >> 6;
        int c4 = (f4 & 63) * 4;
        cp16(s2u(buf + r * 256 + c4), W + (size_t)(k0 + r) * 256 + c4);
    }
    CP_COMMIT();
}

__global__ __launch_bounds__(256) void kout(const float* __restrict__ Wout,
                                            const float* __restrict__ bout,
                                            float* __restrict__ out)
{
    extern __shared__ float sk[];
    float* xs  = sk;                 // 2048 floats
    float* wb0 = sk + 2048;          // 8192
    float* wb1 = sk + 2048 + 8192;   // 8192

    int q0  = blockIdx.x * 8;
    int tid = threadIdx.x;

    stage_out(Wout, 0,  wb0, tid);
    stage_out(Wout, 32, wb1, tid);

    for (int i = tid; i < 2048; i += 256)
        xs[i] = g_outcore[(size_t)q0 * 256 + i];

    float acc[8];
    #pragma unroll
    for (int i = 0; i < 8; ++i) acc[i] = 0.f;

    for (int t = 0; t < 8; ++t) {
        if (t < 7) { CP_WAIT_1(); } else { CP_WAIT_0(); }
        __syncthreads();
        const float* buf = (t & 1) ? wb1 : wb0;
        #pragma unroll 4
        for (int r = 0; r < 32; ++r) {
            float w = buf[r * 256 + tid];
            int k = t * 32 + r;
            #pragma unroll
            for (int i = 0; i < 8; ++i)
                acc[i] = fmaf(xs[i * 256 + k], w, acc[i]);
        }
        __syncthreads();
        if (t + 2 < 8)
            stage_out(Wout, (t + 2) * 32, (t & 1) ? wb1 : wb0, tid);
    }

    float b = bout[tid];
    #pragma unroll
    for (int i = 0; i < 8; ++i)
        out[(size_t)(q0 + i) * 256 + tid] = acc[i] + b;
}

// ---------------------------------------------------------------------------
// Launch
// ---------------------------------------------------------------------------
extern "C" void kernel_launch(void* const* d_in, const int* in_sizes, int n_in,
                              void* d_out, int out_size)
{
    const float* query = (const float*)d_in[0];
    const float* masks = (const float*)d_in[2];
    const float* input = (const float*)d_in[4];
    const float* Woff  = (const float*)d_in[8];
    const float* boff  = (const float*)d_in[9];
    const float* Wattn = (const float*)d_in[10];
    const float* battn = (const float*)d_in[11];
    const float* Wval  = (const float*)d_in[12];
    const float* bval  = (const float*)d_in[13];
    const float* Wout  = (const float*)d_in[14];
    const float* bout  = (const float*)d_in[15];
    float* out = (float*)d_out;

    static const int SMEM_PP  = (4096 + 2 * 12288) * 4;   // 114688
    static const int SMEM_OUT = (2048 + 2 * 8192) * 4;    // 73728

    cudaFuncSetAttribute(kprojpts, cudaFuncAttributeMaxDynamicSharedMemorySize, SMEM_PP);
    cudaFuncSetAttribute(kout,     cudaFuncAttributeMaxDynamicSharedMemorySize, SMEM_OUT);

    kbox    <<<NQ, 256>>>(masks);
    kprojpts<<<150, 256, SMEM_PP>>>(query, Woff, boff, Wattn, battn);
    ksamp   <<<NQ, 256>>>(input, Wval, bval);
    kout    <<<300, 256, SMEM_OUT>>>(Wout, bout, out);
}

// round 17
// speedup vs baseline: 1.0301x; 1.0301x over previous
#include <cuda_runtime.h>
#include <cstdint>

// ---------------------------------------------------------------------------
// Problem constants (hardcoded from the reference)
// ---------------------------------------------------------------------------
#define N_B    8
#define LQ     300
#define NQ     2400        // N_B * LQ
#define C_DIM  256
#define HEADS  8
#define NLVL   4
#define NPTS   8
#define LEN_IN 21760
// level starts: 0, 16384, 20480, 21504  (sizes 128^2, 64^2, 32^2, 16^2)

// ---------------------------------------------------------------------------
// Scratch (device globals — no allocation allowed)
// ---------------------------------------------------------------------------
__device__ uint32_t g_packed[NQ * 512];          // 1-bit mask per (n,q): 128x128 bits
__device__ float    g_boxes[NQ * 4];             // cx, cy, w, h
__device__ float    g_locs[NQ * 512];            // 256 points * (x,y)
__device__ float    g_wts[NQ * 256];             // softmaxed weights
__device__ float    g_agg[NQ * 8 * 256];         // per (n,q,head): aggregated 256-vec
__device__ float    g_beta[NQ * 8];              // per (n,q,head): sum of valid corner wts
__device__ float    g_outcore[NQ * 256];         // pre-output-projection

// ---------------------------------------------------------------------------
// cp.async helpers
// ---------------------------------------------------------------------------
__device__ __forceinline__ uint32_t s2u(const void* p) {
    return (uint32_t)__cvta_generic_to_shared(p);
}
__device__ __forceinline__ void cp16(uint32_t dst, const void* src) {
    asm volatile("cp.async.cg.shared.global [%0], [%1], 16;" :: "r"(dst), "l"(src));
}
#define CP_COMMIT()  asm volatile("cp.async.commit_group;" ::: "memory")
#define CP_WAIT_1()  asm volatile("cp.async.wait_group 1;" ::: "memory")
#define CP_WAIT_0()  asm volatile("cp.async.wait_group 0;" ::: "memory")

// ---------------------------------------------------------------------------
// Kernel 1: bounding boxes + packed binary masks  (pure float4 streamer)
// grid = NQ blocks, 256 threads. Thread t handles 64 contiguous elements.
// ---------------------------------------------------------------------------
__global__ __launch_bounds__(256) void kbox(const float* __restrict__ masks)
{
    int nq   = blockIdx.x;
    int tid  = threadIdx.x;
    int row  = tid >> 1;
    int half = tid & 1;

    __shared__ unsigned scol[4];   // per-x "any over y" bits (128 cols)
    __shared__ unsigned srow[4];   // per-y "any over x" bits (128 rows)
    if (tid < 4) { scol[tid] = 0u; srow[tid] = 0u; }
    __syncthreads();

    const float4* p = (const float4*)(masks + (size_t)nq * 16384 + tid * 64);

    unsigned w0 = 0u, w1 = 0u;
    #pragma unroll
    for (int j = 0; j < 8; ++j) {
        float4 v = p[j];
        unsigned b = (v.x > 0.0f ? 1u : 0u)
                   | (v.y > 0.0f ? 2u : 0u)
                   | (v.z > 0.0f ? 4u : 0u)
                   | (v.w > 0.0f ? 8u : 0u);
        w0 |= b << (j * 4);
    }
    #pragma unroll
    for (int j = 8; j < 16; ++j) {
        float4 v = p[j];
        unsigned b = (v.x > 0.0f ? 1u : 0u)
                   | (v.y > 0.0f ? 2u : 0u)
                   | (v.z > 0.0f ? 4u : 0u)
                   | (v.w > 0.0f ? 8u : 0u);
        w1 |= b << ((j - 8) * 4);
    }

    uint32_t* pk = g_packed + (size_t)nq * 512 + row * 4 + half * 2;
    pk[0] = w0;
    pk[1] = w1;

    if (w0) atomicOr(&scol[half * 2], w0);
    if (w1) atomicOr(&scol[half * 2 + 1], w1);

    unsigned any = (w0 | w1) ? 1u : 0u;
    unsigned both = any | __shfl_xor_sync(0xffffffffu, any, 1);
    if (half == 0 && both)
        atomicOr(&srow[row >> 5], 1u << (row & 31));
    __syncthreads();

    if (tid == 0) {
        unsigned anyc = scol[0] | scol[1] | scol[2] | scol[3];
        float bx0 = 0.f, bx1 = 0.f, bx2 = 0.f, bx3 = 0.f;
        if (anyc) {
            int xmin = 0, xmax = 0, ymin = 0, ymax = 0;
            #pragma unroll
            for (int i = 3; i >= 0; --i) if (scol[i]) xmin = i * 32 + __ffs((int)scol[i]) - 1;
            #pragma unroll
            for (int i = 0; i < 4; ++i)  if (scol[i]) xmax = i * 32 + 31 - __clz((int)scol[i]);
            #pragma unroll
            for (int i = 3; i >= 0; --i) if (srow[i]) ymin = i * 32 + __ffs((int)srow[i]) - 1;
            #pragma unroll
            for (int i = 0; i < 4; ++i)  if (srow[i]) ymax = i * 32 + 31 - __clz((int)srow[i]);
            float x0 = xmin * (1.0f / 128.0f), x1 = (xmax + 1) * (1.0f / 128.0f);
            float y0 = ymin * (1.0f / 128.0f), y1 = (ymax + 1) * (1.0f / 128.0f);
            bx0 = (x0 + x1) * 0.5f;
            bx1 = (y0 + y1) * 0.5f;
            bx2 = x1 - x0;
            bx3 = y1 - y0;
        }
        *(float4*)(g_boxes + nq * 4) = make_float4(bx0, bx1, bx2, bx3);
    }
}

// ---------------------------------------------------------------------------
// Kernel 2 (fused): projections (cp.async double-buffered), locations,
// point-in-mask, per-head softmax.
// grid = 150 blocks (16 queries), 256 threads.
// dyn smem: qs[16*256] + 2 x wtile[16*768]   (112 KB)
// ---------------------------------------------------------------------------
__device__ __forceinline__ void stage_pp(const float* __restrict__ Woff,
                                         const float* __restrict__ Wattn,
                                         int k0, float* buf, int tid)
{
    #pragma unroll
    for (int j = 0; j < 12; ++j) {
        int idx = tid + j * 256;               // float4 index in tile, 0..3071
        int r   = idx / 192;                   // 192 float4 per row (512+256 floats)
        int c4  = idx - r * 192;
        const float* src = (c4 < 128)
            ? (Woff  + (size_t)(k0 + r) * 512 + c4 * 4)
            : (Wattn + (size_t)(k0 + r) * 256 + (c4 - 128) * 4);
        cp16(s2u(buf + r * 768 + c4 * 4), src);
    }
    CP_COMMIT();
}

__global__ __launch_bounds__(256) void kprojpts(const float* __restrict__ query,
                                                const float* __restrict__ Woff,
                                                const float* __restrict__ boff,
                                                const float* __restrict__ Wattn,
                                                const float* __restrict__ battn)
{
    extern __shared__ float sm[];
    float* qs  = sm;                 // 4096 floats
    float* wb0 = sm + 4096;          // 12288 floats
    float* wb1 = sm + 4096 + 12288;  // 12288 floats

    int tid = threadIdx.x;
    int q0  = blockIdx.x * 16;

    stage_pp(Woff, Wattn, 0,  wb0, tid);
    stage_pp(Woff, Wattn, 16, wb1, tid);

    for (int i = tid; i < 16 * 256; i += 256)
        qs[i] = query[(size_t)q0 * 256 + i];

    float acc0[16], acc1[16], acc2[16];
    #pragma unroll
    for (int i = 0; i < 16; ++i) { acc0[i] = 0.f; acc1[i] = 0.f; acc2[i] = 0.f; }

    for (int t = 0; t < 16; ++t) {
        if (t < 15) { CP_WAIT_1(); } else { CP_WAIT_0(); }
        __syncthreads();
        const float* buf = (t & 1) ? wb1 : wb0;
        #pragma unroll 4
        for (int r = 0; r < 16; ++r) {
            float w0 = buf[r * 768 + tid];
            float w1 = buf[r * 768 + 256 + tid];
            float w2 = buf[r * 768 + 512 + tid];
            int k = t * 16 + r;
            #pragma unroll
            for (int i = 0; i < 16; ++i) {
                float qv = qs[i * 256 + k];
                acc0[i] = fmaf(qv, w0, acc0[i]);
                acc1[i] = fmaf(qv, w1, acc1[i]);
                acc2[i] = fmaf(qv, w2, acc2[i]);
            }
        }
        __syncthreads();
        if (t + 2 < 16)
            stage_pp(Woff, Wattn, (t + 2) * 16, (t & 1) ? wb1 : wb0, tid);
    }

    // write projection results (+bias) into the wb0 region: res[16][768]
    float* res = wb0;
    {
        float b0 = boff[tid], b1 = boff[256 + tid], b2 = battn[tid];
        #pragma unroll
        for (int i = 0; i < 16; ++i) {
            res[i * 768 + tid]       = acc0[i] + b0;
            res[i * 768 + 256 + tid] = acc1[i] + b1;
            res[i * 768 + 512 + tid] = acc2[i] + b2;
        }
    }
    __syncthreads();

    // Phase B: thread tid = sample s (warp = head)
    int s = tid;
    for (int qi = 0; qi < 16; ++qi) {
        int nq = q0 + qi;
        float4 bx = *(const float4*)(g_boxes + nq * 4);
        float ox = res[qi * 768 + 2 * s];
        float oy = res[qi * 768 + 2 * s + 1];
        float at = res[qi * 768 + 512 + s];

        float lx = bx.x + ox * (bx.z * 0.0625f);
        float ly = bx.y + oy * (bx.w * 0.0625f);

        int px = (int)(lx * 128.0f); px = min(max(px, 0), 127);
        int py = (int)(ly * 128.0f); py = min(max(py, 0), 127);
        unsigned bit = (g_packed[(size_t)nq * 512 + py * 4 + (px >> 5)] >> (px & 31)) & 1u;

        float e = at * (float)bit;

        float mx = e;
        #pragma unroll
        for (int o = 16; o > 0; o >>= 1) mx = fmaxf(mx, __shfl_xor_sync(0xffffffffu, mx, o));
        float ex = expf(e - mx);
        float smv = ex;
        #pragma unroll
        for (int o = 16; o > 0; o >>= 1) smv += __shfl_xor_sync(0xffffffffu, smv, o);
        float w = ex / smv;

        ((float2*)(g_locs + (size_t)nq * 512))[s] = make_float2(lx, ly);
        g_wts[(size_t)nq * 256 + s] = w;
    }
}

// ---------------------------------------------------------------------------
// Kernel 3 (hot): bilinear gather + weighted aggregation of full input rows
// grid = NQ blocks, 8 warps (warp = head). Lane owns 8 channels.
// ---------------------------------------------------------------------------
__global__ __launch_bounds__(256) void ksamp(const float* __restrict__ input)
{
    int nq   = blockIdx.x;
    int n    = nq / LQ;
    int warp = threadIdx.x >> 5;
    int lane = threadIdx.x & 31;

    const float* base = input + (size_t)n * (LEN_IN * C_DIM);

    float2 L = ((const float2*)(g_locs + (size_t)nq * 512))[warp * 32 + lane];
    float  Wt = g_wts[(size_t)nq * 256 + warp * 32 + lane];
    float  Lx = L.x, Ly = L.y;

    float acc[8] = {0.f, 0.f, 0.f, 0.f, 0.f, 0.f, 0.f, 0.f};
    float bacc = 0.f;

#define CORNER(XI, YI, CWV)                                                     \
    do {                                                                        \
        int _x = (XI), _y = (YI);                                               \
        if (_x >= 0 && _x < Wl && _y >= 0 && _y < Wl) {                         \
            float _cw = (CWV);                                                  \
            const float4* _r = (const float4*)(baseL +                          \
                               (size_t)(_y * Wl + _x) * C_DIM);                 \
            float4 _v0 = _r[lane];                                              \
            float4 _v1 = _r[32 + lane];                                         \
            acc[0] = fmaf(_cw, _v0.x, acc[0]);                                  \
            acc[1] = fmaf(_cw, _v0.y, acc[1]);                                  \
            acc[2] = fmaf(_cw, _v0.z, acc[2]);                                  \
            acc[3] = fmaf(_cw, _v0.w, acc[3]);                                  \
            acc[4] = fmaf(_cw, _v1.x, acc[4]);                                  \
            acc[5] = fmaf(_cw, _v1.y, acc[5]);                                  \
            acc[6] = fmaf(_cw, _v1.z, acc[6]);                                  \
            acc[7] = fmaf(_cw, _v1.w, acc[7]);                                  \
            bacc += _cw;                                                        \
        }                                                                       \
    } while (0)

    #pragma unroll
    for (int l = 0; l < 4; ++l) {
        const int Wl     = 128 >> l;
        const int startl = (l == 0) ? 0 : (l == 1) ? 16384 : (l == 2) ? 20480 : 21504;
        const float fW   = (float)Wl;
        const float* baseL = base + (size_t)startl * C_DIM;
        #pragma unroll
        for (int p = 0; p < 8; ++p) {
            int s = l * 8 + p;
            float lx = __shfl_sync(0xffffffffu, Lx, s);
            float ly = __shfl_sync(0xffffffffu, Ly, s);
            float wt = __shfl_sync(0xffffffffu, Wt, s);

            float px = lx * fW - 0.5f;
            float py = ly * fW - 0.5f;
            float xf = floorf(px), yf = floorf(py);
            float fx = px - xf,    fy = py - yf;
            int   x0 = (int)xf,    y0 = (int)yf;
            float gx = 1.0f - fx,  gy = 1.0f - fy;

            CORNER(x0,     y0,     wt * gx * gy);
            CORNER(x0 + 1, y0,     wt * fx * gy);
            CORNER(x0,     y0 + 1, wt * gx * fy);
            CORNER(x0 + 1, y0 + 1, wt * fx * fy);
        }
    }
#undef CORNER

    float* ap = g_agg + ((size_t)nq * 8 + warp) * 256;
    ((float4*)ap)[lane]      = make_float4(acc[0], acc[1], acc[2], acc[3]);
    ((float4*)ap)[32 + lane] = make_float4(acc[4], acc[5], acc[6], acc[7]);
    if (lane == 0)
        g_beta[nq * 8 + warp] = bacc;
}

// ---------------------------------------------------------------------------
// Kernel 4 v3: per-head value projection, register-tiled, 256 threads
// grid = (75, 8): 32 queries x head h. Thread computes 1 query x 4 d.
// dyn smem: as[32*260] + ws[256*32]  (66 KB, 3 blocks/SM, 24 warps = 50% occ)
// ---------------------------------------------------------------------------
__global__ __launch_bounds__(256) void khead(const float* __restrict__ Wval,
                                             const float* __restrict__ bval)
{
    extern __shared__ float sh[];
    float* as = sh;                  // 32 * 260 (pad -> conflict-free + 16B aligned)
    float* ws = sh + 32 * 260;       // 256 * 32

    int h   = blockIdx.y;
    int q0  = blockIdx.x * 32;
    int tid = threadIdx.x;

    // stage agg tile: 2048 float4, 8 per thread (high MLP, coalesced)
    #pragma unroll
    for (int j = 0; j < 8; ++j) {
        int f4 = tid + j * 256;          // 0..2047
        int q  = f4 >> 6;                // 64 float4 per query row
        int c  = (f4 & 63) * 4;
        float4 v = *(const float4*)(g_agg + ((size_t)(q0 + q) * 8 + h) * 256 + c);
        *(float4*)(as + q * 260 + c) = v;
    }
    // stage Wval head slice: 2048 float4, 8 per thread
    #pragma unroll
    for (int j = 0; j < 8; ++j) {
        int f4 = tid + j * 256;
        int c  = f4 >> 3;
        int dd = (f4 & 7) * 4;
        *(float4*)(ws + c * 32 + dd) =
            *(const float4*)(Wval + (size_t)c * 256 + h * 32 + dd);
    }
    __syncthreads();

    int dg = (tid & 7) * 4;          // d-group within head
    int q  = tid >> 3;               // query 0..31

    float a0 = 0.f, a1 = 0.f, a2 = 0.f, a3 = 0.f;
    const float* asr = as + q * 260;

    #pragma unroll 8
    for (int c = 0; c < 256; ++c) {
        float4 w = *(const float4*)(ws + c * 32 + dg);
        float x = asr[c];
        a0 = fmaf(x, w.x, a0);
        a1 = fmaf(x, w.y, a1);
        a2 = fmaf(x, w.z, a2);
        a3 = fmaf(x, w.w, a3);
    }

    int d = h * 32 + dg;
    float4 bv = *(const float4*)(bval + d);
    float be = g_beta[(q0 + q) * 8 + h];
    *(float4*)(g_outcore + (size_t)(q0 + q) * 256 + d) =
        make_float4(a0 + be * bv.x, a1 + be * bv.y,
                    a2 + be * bv.z, a3 + be * bv.w);
}

// ---------------------------------------------------------------------------
// Kernel 5 v3: output projection, cp.async double-buffered 16-row tiles
// grid = 300 blocks (8 queries), 256 threads.
// dyn smem: xs[8*256] + 2 x wtile[16*256]  (40 KB -> 5 blocks/SM)
// ---------------------------------------------------------------------------
__device__ __forceinline__ void stage_out(const float* __restrict__ W,
                                          int k0, float* buf, int tid)
{
    #pragma unroll
    for (int j = 0; j < 4; ++j) {
        int f4 = tid + j * 256;          // 0..1023
        int r  = f4 >> 6;
        int c4 = (f4 & 63) * 4;
        cp16(s2u(buf + r * 256 + c4), W + (size_t)(k0 + r) * 256 + c4);
    }
    CP_COMMIT();
}

__global__ __launch_bounds__(256) void kout(const float* __restrict__ Wout,
                                            const float* __restrict__ bout,
                                            float* __restrict__ out)
{
    extern __shared__ float sk[];
    float* xs  = sk;                 // 2048 floats
    float* wb0 = sk + 2048;          // 4096
    float* wb1 = sk + 2048 + 4096;   // 4096

    int q0  = blockIdx.x * 8;
    int tid = threadIdx.x;

    stage_out(Wout, 0,  wb0, tid);
    stage_out(Wout, 16, wb1, tid);

    for (int i = tid; i < 2048; i += 256)
        xs[i] = g_outcore[(size_t)q0 * 256 + i];

    float acc[8];
    #pragma unroll
    for (int i = 0; i < 8; ++i) acc[i] = 0.f;

    for (int t = 0; t < 16; ++t) {
        if (t < 15) { CP_WAIT_1(); } else { CP_WAIT_0(); }
        __syncthreads();
        const float* buf = (t & 1) ? wb1 : wb0;
        #pragma unroll 4
        for (int r = 0; r < 16; ++r) {
            float w = buf[r * 256 + tid];
            int k = t * 16 + r;
            #pragma unroll
            for (int i = 0; i < 8; ++i)
                acc[i] = fmaf(xs[i * 256 + k], w, acc[i]);
        }
        __syncthreads();
        if (t + 2 < 16)
            stage_out(Wout, (t + 2) * 16, (t & 1) ? wb1 : wb0, tid);
    }

    float b = bout[tid];
    #pragma unroll
    for (int i = 0; i < 8; ++i)
        out[(size_t)(q0 + i) * 256 + tid] = acc[i] + b;
}

// ---------------------------------------------------------------------------
// Launch
// ---------------------------------------------------------------------------
extern "C" void kernel_launch(void* const* d_in, const int* in_sizes, int n_in,
                              void* d_out, int out_size)
{
    const float* query = (const float*)d_in[0];
    const float* masks = (const float*)d_in[2];
    const float* input = (const float*)d_in[4];
    const float* Woff  = (const float*)d_in[8];
    const float* boff  = (const float*)d_in[9];
    const float* Wattn = (const float*)d_in[10];
    const float* battn = (const float*)d_in[11];
    const float* Wval  = (const float*)d_in[12];
    const float* bval  = (const float*)d_in[13];
    const float* Wout  = (const float*)d_in[14];
    const float* bout  = (const float*)d_in[15];
    float* out = (float*)d_out;

    static const int SMEM_PP   = (4096 + 2 * 12288) * 4;    // 114688
    static const int SMEM_HEAD = (32 * 260 + 256 * 32) * 4; // 66048
    static const int SMEM_OUT  = (2048 + 2 * 4096) * 4;     // 40960

    cudaFuncSetAttribute(kprojpts, cudaFuncAttributeMaxDynamicSharedMemorySize, SMEM_PP);
    cudaFuncSetAttribute(khead,    cudaFuncAttributeMaxDynamicSharedMemorySize, SMEM_HEAD);
    cudaFuncSetAttribute(kout,     cudaFuncAttributeMaxDynamicSharedMemorySize, SMEM_OUT);

    kbox    <<<NQ, 256>>>(masks);
    kprojpts<<<150, 256, SMEM_PP>>>(query, Woff, boff, Wattn, battn);
    ksamp   <<<NQ, 256>>>(input);
    khead   <<<dim3(75, 8), 256, SMEM_HEAD>>>(Wval, bval);
    kout    <<<300, 256, SMEM_OUT>>>(Wout, bout, out);
}